// round 15
// baseline (speedup 1.0000x reference)
#include <cuda_runtime.h>
#include <cstdint>

// image: [64, 3, 512, 512] fp32; mask [64,64] bool-as-int32 (rate ~0.5).
// out = where(mask8x8, -1.0f, image).
//
// R14 probe: DENSE loads (no predication) + cache hints. Rationale: the
// predication-gapped read stream lowers DRAM burst efficiency (6065 GB/s)
// vs dense (6341 GB/s in R3); byte savings and BW loss roughly cancel, but
// dense + __ldcg/__stcs was never measured. UNROLL=4, 256 TPB, exact grid.

#define W4 128            // float4s per row (W=512)
#define UNROLL 4

__global__ void __launch_bounds__(256) grid_crop_kernel(
    const float4* __restrict__ img,
    const int* __restrict__ sw,      // [64,64] bool-as-int32
    float4* __restrict__ out)
{
    int base = blockIdx.x * (256 * UNROLL) + threadIdx.x;

    int idx[UNROLL];
    int m[UNROLL];
    float4 v[UNROLL];

    // Dense front-batched loads: 4 independent LDG.128, no gaps.
    #pragma unroll
    for (int k = 0; k < UNROLL; k++) {
        idx[k] = base + k * 256;
        v[k] = __ldcg(&img[idx[k]]);
    }

    #pragma unroll
    for (int k = 0; k < UNROLL; k++) {
        int w4 = idx[k] & (W4 - 1);          // 0..127
        int h  = (idx[k] >> 7) & 511;        // 0..511
        m[k] = __ldg(&sw[((h >> 3) << 6) | (w4 >> 1)]);
        if (m[k]) { v[k].x = -1.0f; v[k].y = -1.0f; v[k].z = -1.0f; v[k].w = -1.0f; }
    }

    // Evict-first streaming stores.
    #pragma unroll
    for (int k = 0; k < UNROLL; k++) {
        __stcs(&out[idx[k]], v[k]);
    }
}

extern "C" void kernel_launch(void* const* d_in, const int* in_sizes, int n_in,
                              void* d_out, int out_size)
{
    const void* p_img = d_in[0];
    const void* p_sw  = d_in[1];
    if (n_in >= 2 && in_sizes[0] < in_sizes[1]) {
        p_img = d_in[1];
        p_sw  = d_in[0];
    }

    const float4* img = (const float4*)p_img;
    const int* sw = (const int*)p_sw;
    float4* out = (float4*)d_out;

    int n4 = out_size / 4;                      // 12,582,912
    int blocks = n4 / (256 * UNROLL);           // 12,288 exact
    grid_crop_kernel<<<blocks, 256>>>(img, sw, out);
}

// round 17
// speedup vs baseline: 1.0248x; 1.0248x over previous
#include <cuda_runtime.h>
#include <cstdint>

// image: [64, 3, 512, 512] fp32; mask [64,64] bool-as-int32 (rate ~0.5).
// out = where(mask8x8, -1.0f, image).
//
// FINAL champion (reproduced 4x at 61.9-62.1us wall, ~55us kernel, ~96% of
// the 335MB @ 6.34TB/s bandwidth floor). Beats dense-load variant (63.3-63.5)
// by skipping fully-masked 128B lines (~12MB/launch) at minor burst-eff cost.
//   - UNROLL=4: 4 independent predicated LDG.128 per thread (MLP=4)
//   - 256 threads/block, exact grid (12288 blocks, no tail, no bounds checks)
//   - __ldcg image loads: L2-only, no L1 allocation (single-use data)
//   - __stcs stores: evict-first streaming writes
//   - mask lookups via __ldg: 16KB, L1-resident, warp-broadcast friendly

#define W4 128            // float4s per row (W=512)
#define UNROLL 4

__global__ void __launch_bounds__(256) grid_crop_kernel(
    const float4* __restrict__ img,
    const int* __restrict__ sw,      // [64,64] bool-as-int32
    float4* __restrict__ out)
{
    int base = blockIdx.x * (256 * UNROLL) + threadIdx.x;

    int idx[UNROLL];
    int m[UNROLL];
    float4 v[UNROLL];

    // Mask lookups (L1-resident, broadcast across 8 adjacent threads).
    #pragma unroll
    for (int k = 0; k < UNROLL; k++) {
        idx[k] = base + k * 256;
        int w4 = idx[k] & (W4 - 1);          // 0..127
        int h  = (idx[k] >> 7) & 511;        // 0..511
        m[k] = __ldg(&sw[((h >> 3) << 6) | (w4 >> 1)]);
    }

    // Predicated L2-only loads: fully-masked 128B lines never fetched.
    #pragma unroll
    for (int k = 0; k < UNROLL; k++) {
        v[k] = make_float4(-1.0f, -1.0f, -1.0f, -1.0f);
        if (!m[k]) v[k] = __ldcg(&img[idx[k]]);
    }

    // Evict-first streaming stores.
    #pragma unroll
    for (int k = 0; k < UNROLL; k++) {
        __stcs(&out[idx[k]], v[k]);
    }
}

extern "C" void kernel_launch(void* const* d_in, const int* in_sizes, int n_in,
                              void* d_out, int out_size)
{
    const void* p_img = d_in[0];
    const void* p_sw  = d_in[1];
    if (n_in >= 2 && in_sizes[0] < in_sizes[1]) {
        p_img = d_in[1];
        p_sw  = d_in[0];
    }

    const float4* img = (const float4*)p_img;
    const int* sw = (const int*)p_sw;
    float4* out = (float4*)d_out;

    int n4 = out_size / 4;                      // 12,582,912
    int blocks = n4 / (256 * UNROLL);           // 12,288 exact
    grid_crop_kernel<<<blocks, 256>>>(img, sw, out);
}